// round 10
// baseline (speedup 1.0000x reference)
#include <cuda_runtime.h>

#define BSZ 2
#define LSEQ 2048
#define DIMC 1024
#define HAR 32
#define NH 16
#define HD 64
#define LOG2E 1.4426950408889634f
#define SCALE 0.125f

// ---------------- scratch (__device__ globals; no allocation allowed) ----------------
__device__ float g_res[3 * BSZ * LSEQ * HAR];   // res_q/res_k/res_v  [3][B][L][32]
__device__ float g_rkT[BSZ * HAR * LSEQ];       // res_k transposed   [B][32][L]
__device__ float g_M[NH * HAR * HAR];           // M_h[i][j] * scale * log2e
__device__ float g_C[NH * HAR * HAR];           // C_h[j][g]
__device__ float g_wo[DIMC * HAR];              // wo[o][g]
__device__ float g_U[BSZ * NH * LSEQ * HAR];    // attention U  [B][H][L][32]
__device__ float g_ro[BSZ * LSEQ * HAR];        // res_o        [B*L][32]

typedef unsigned long long u64;

__device__ __forceinline__ u64 pk2(float x, float y) {
    u64 r; asm("mov.b64 %0, {%1,%2};" : "=l"(r) : "f"(x), "f"(y)); return r;
}
__device__ __forceinline__ float2 upk2(u64 a) {
    float2 r; asm("mov.b64 {%0,%1}, %2;" : "=f"(r.x), "=f"(r.y) : "l"(a)); return r;
}
__device__ __forceinline__ u64 fma2(u64 a, u64 b, u64 c) {
    u64 d; asm("fma.rn.f32x2 %0, %1, %2, %3;" : "=l"(d) : "l"(a), "l"(b), "l"(c)); return d;
}
__device__ __forceinline__ u64 mul2(u64 a, u64 b) {
    u64 d; asm("mul.rn.f32x2 %0, %1, %2;" : "=l"(d) : "l"(a), "l"(b)); return d;
}
__device__ __forceinline__ u64 add2(u64 a, u64 b) {
    u64 d; asm("add.rn.f32x2 %0, %1, %2;" : "=l"(d) : "l"(a), "l"(b)); return d;
}
__device__ __forceinline__ float ex2f(float x) {
    float r; asm("ex2.approx.ftz.f32 %0, %1;" : "=f"(r) : "f"(x)); return r;
}
__device__ __forceinline__ void cpa16(unsigned dst, const void* src) {
    asm volatile("cp.async.cg.shared.global [%0], [%1], 16;" :: "r"(dst), "l"(src));
}
__device__ __forceinline__ void cpa_commit() {
    asm volatile("cp.async.commit_group;" ::: "memory");
}

// ---------------- K1: per-head M_h and C_h ----------------
__global__ void k_mc(const float* __restrict__ aq, const float* __restrict__ pq,
                     const float* __restrict__ ak, const float* __restrict__ pkh,
                     const float* __restrict__ av, const float* __restrict__ pv,
                     const float* __restrict__ bo) {
    int h = blockIdx.x, t = threadIdx.x;
    __shared__ float wq[HD * HAR], wk[HD * HAR], wv[HD * HAR], bos[HD * HAR];
    for (int e = t; e < HD * HAR; e += 1024) {
        int d = e >> 5, i = e & 31;
        int idx = (h * HD + d) * HAR + i;
        wq[e]  = aq[idx] * (float)cos((double)pq[idx]);   // fp64 cos: immune to fast_math
        wk[e]  = ak[idx] * (float)cos((double)pkh[idx]);
        wv[e]  = av[idx] * (float)cos((double)pv[idx]);
        bos[e] = bo[i * DIMC + h * HD + d];
    }
    __syncthreads();
    int i = t >> 5, j = t & 31;
    float m = 0.f, c = 0.f;
    #pragma unroll 8
    for (int d = 0; d < HD; d++) {
        m += wq[d * 32 + i] * wk[d * 32 + j];
        c += wv[d * 32 + i] * bos[d * 32 + j];
    }
    g_M[h * 1024 + t] = m * (SCALE * LOG2E);
    g_C[h * 1024 + t] = c;
}

// ---------------- K2: wo = amp_o * cos(phase_o) ----------------
__global__ void k_wo(const float* __restrict__ ao, const float* __restrict__ po) {
    int i = blockIdx.x * 1024 + threadIdx.x;
    g_wo[i] = ao[i] * (float)cos((double)po[i]);
}

// ---------------- K3: resonance GEMM  [4096,1024] x [1024,96] ----------------
__global__ __launch_bounds__(256) void k_res(const float* __restrict__ x,
                                             const float* __restrict__ bq,
                                             const float* __restrict__ bk,
                                             const float* __restrict__ bv) {
    __shared__ __align__(16) float As[32 * 33];
    __shared__ __align__(16) float Bs[32 * 97];
    int t = threadIdx.x;
    int r0 = blockIdx.x * 32;
    int tx = t & 15, ty = t >> 4;
    float acc[2][6];
    #pragma unroll
    for (int u = 0; u < 2; u++)
        #pragma unroll
        for (int c = 0; c < 6; c++) acc[u][c] = 0.f;

    for (int k0 = 0; k0 < DIMC; k0 += 32) {
        __syncthreads();
        {
            int row = t >> 3, c4 = (t & 7) * 4;
            float4 v = *(const float4*)(x + (r0 + row) * DIMC + k0 + c4);
            float* d = As + row * 33 + c4;
            d[0] = v.x; d[1] = v.y; d[2] = v.z; d[3] = v.w;
        }
        for (int f4 = t; f4 < 768; f4 += 256) {
            int n = f4 >> 3, c4 = (f4 & 7) * 4;
            const float* bp = (n < 32) ? (bq + n * DIMC)
                             : (n < 64) ? (bk + (n - 32) * DIMC)
                                        : (bv + (n - 64) * DIMC);
            float4 v = *(const float4*)(bp + k0 + c4);
            Bs[(c4 + 0) * 97 + n] = v.x;
            Bs[(c4 + 1) * 97 + n] = v.y;
            Bs[(c4 + 2) * 97 + n] = v.z;
            Bs[(c4 + 3) * 97 + n] = v.w;
        }
        __syncthreads();
        #pragma unroll
        for (int kk = 0; kk < 32; kk++) {
            float a0 = As[(ty * 2 + 0) * 33 + kk];
            float a1 = As[(ty * 2 + 1) * 33 + kk];
            #pragma unroll
            for (int c = 0; c < 6; c++) {
                float bb = Bs[kk * 97 + tx * 6 + c];
                acc[0][c] += a0 * bb;
                acc[1][c] += a1 * bb;
            }
        }
    }
    #pragma unroll
    for (int u = 0; u < 2; u++)
        #pragma unroll
        for (int c = 0; c < 6; c++) {
            int row = r0 + ty * 2 + u;
            int n = tx * 6 + c;
            int p = n >> 5, j = n & 31;
            int b = row >> 11, l = row & (LSEQ - 1);
            if (p == 1)
                g_rkT[(b * HAR + j) * LSEQ + l] = acc[u][c];     // K transposed
            else
                g_res[((p * BSZ + b) * LSEQ + l) * HAR + j] = acc[u][c];
        }
}

// ---------------- K4: fused flash attention on rank-32 factors ----------------
// grid (64 qtiles of 32, B*H=32), 128 threads = 4 warps.
// Lane (qsub,ksub) owns 2 queries x 16 keys; key-chunk order is ROTATED by
// qsub (ctt = (tt+qsub)&3) so every lane of an LDS.128 reads a DISTINCT 16B
// chunk -> raw crossbar traffic drops 4x to the information floor.
// Logits tiny (|S|<<1): plain exp2, no max subtraction; l reduced at the end.
#define KTBUF (32 * 132)
#define VBUF  (128 * 36)
__global__ __launch_bounds__(128, 3) void k_attn() {
    extern __shared__ __align__(16) float smem[];
    float* sKT = smem;                       // 2 x KTBUF
    float* sV  = smem + 2 * KTBUF;           // 2 x VBUF
    float* sGq = smem + 2 * KTBUF + 2 * VBUF;// 32 x 34

    int t = threadIdx.x;
    int w = t >> 5, lane = t & 31;
    int qsub = lane >> 3, ksub = lane & 7;
    int q0 = blockIdx.x * 32;
    int bh = blockIdx.y;
    int b = bh >> 4, h = bh & 15;
    const float* rq  = g_res + (0 * BSZ + b) * LSEQ * HAR;
    const float* rv  = g_res + (2 * BSZ + b) * LSEQ * HAR;
    const float* rkT = g_rkT + b * HAR * LSEQ;

    // rotation offsets (in floats): chunk ctt = (tt+qsub)&3 at step tt
    int rot[4];
    #pragma unroll
    for (int tt = 0; tt < 4; tt++) rot[tt] = (((tt + qsub) & 3) * 32);

    // ---- stage tile 0 into buffer 0 ----
    {
        unsigned kbase = (unsigned)__cvta_generic_to_shared(sKT);
        unsigned vbase = (unsigned)__cvta_generic_to_shared(sV);
        #pragma unroll
        for (int it = 0; it < 8; it++) {
            int f4 = t + it * 128;
            int row = f4 >> 5, c = f4 & 31;
            cpa16(kbase + (row * 132 + c * 4) * 4, rkT + row * LSEQ + c * 4);
        }
        #pragma unroll
        for (int it = 0; it < 8; it++) {
            int f4 = t + it * 128;
            int key = f4 >> 3, gi = f4 & 7;
            int pc = gi ^ ((key >> 2) & 7);
            cpa16(vbase + (key * 36 + pc * 4) * 4, rv + key * HAR + gi * 4);
        }
        cpa_commit();
    }

    // ---- phase 0: Gq = rq_tile[32,32] * M[32,32], stored transposed in sGq ----
    {
        int q = t >> 2, jb = (t & 3) * 8;
        const float* rqrow = rq + (q0 + q) * HAR;
        const float* Mrow = g_M + h * 1024;
        float a[8];
        #pragma unroll
        for (int jj = 0; jj < 8; jj++) a[jj] = 0.f;
        #pragma unroll 4
        for (int i = 0; i < 32; i++) {
            float qv = rqrow[i];
            #pragma unroll
            for (int jj = 0; jj < 8; jj++) a[jj] += qv * Mrow[i * 32 + jb + jj];
        }
        #pragma unroll
        for (int jj = 0; jj < 8; jj++) sGq[(jb + jj) * 34 + q] = a[jj];
    }

    u64 U2[2][16];
    #pragma unroll
    for (int q = 0; q < 2; q++)
        #pragma unroll
        for (int gp = 0; gp < 16; gp++) U2[q][gp] = 0ULL;
    float l0 = 0.f, l1 = 0.f;
    int qb = w * 8 + qsub * 2;

    for (int kt = 0; kt < 16; kt++) {
        int cb = kt & 1;
        if (kt < 15) {       // stage next tile into the other buffer
            int nb = cb ^ 1;
            unsigned kbase = (unsigned)__cvta_generic_to_shared(sKT + nb * KTBUF);
            unsigned vbase = (unsigned)__cvta_generic_to_shared(sV + nb * VBUF);
            const float* rkTs = rkT + (kt + 1) * 128;
            const float* rvs  = rv + (kt + 1) * 128 * HAR;
            #pragma unroll
            for (int it = 0; it < 8; it++) {
                int f4 = t + it * 128;
                int row = f4 >> 5, c = f4 & 31;
                cpa16(kbase + (row * 132 + c * 4) * 4, rkTs + row * LSEQ + c * 4);
            }
            #pragma unroll
            for (int it = 0; it < 8; it++) {
                int f4 = t + it * 128;
                int key = f4 >> 3, gi = f4 & 7;
                int pc = gi ^ ((key >> 2) & 7);
                cpa16(vbase + (key * 36 + pc * 4) * 4, rvs + key * HAR + gi * 4);
            }
            cpa_commit();
            asm volatile("cp.async.wait_group 1;" ::: "memory");
        } else {
            asm volatile("cp.async.wait_group 0;" ::: "memory");
        }
        __syncthreads();

        const float* ktb = sKT + cb * KTBUF;
        const float* vtb = sV + cb * VBUF;

        // ---- S phase: s2[q][slot]; slot tt holds key-chunk ctt=(tt+qsub)&3 ----
        u64 s2[2][8];
        #pragma unroll
        for (int q = 0; q < 2; q++)
            #pragma unroll
            for (int kp = 0; kp < 8; kp++) s2[q][kp] = 0ULL;
        #pragma unroll 4
        for (int kk = 0; kk < 32; kk++) {
            float2 gqv = *(const float2*)(sGq + kk * 34 + qb);  // broadcast
            u64 a0 = pk2(gqv.x, gqv.x);
            u64 a1 = pk2(gqv.y, gqv.y);
            const float* kr = ktb + kk * 132 + ksub * 4;
            #pragma unroll
            for (int tt = 0; tt < 4; tt++) {
                ulonglong2 kv = *(const ulonglong2*)(kr + rot[tt]);  // distinct per lane
                s2[0][tt * 2 + 0] = fma2(a0, kv.x, s2[0][tt * 2 + 0]);
                s2[0][tt * 2 + 1] = fma2(a0, kv.y, s2[0][tt * 2 + 1]);
                s2[1][tt * 2 + 0] = fma2(a1, kv.x, s2[1][tt * 2 + 0]);
                s2[1][tt * 2 + 1] = fma2(a1, kv.y, s2[1][tt * 2 + 1]);
            }
        }

        // ---- p = exp2(s) directly (logits tiny; no max subtraction needed) ----
        #pragma unroll
        for (int kp = 0; kp < 8; kp++) {
            float2 f0 = upk2(s2[0][kp]);
            float px = ex2f(f0.x), py = ex2f(f0.y);
            s2[0][kp] = pk2(px, py); l0 += px + py;
            float2 f1 = upk2(s2[1][kp]);
            float qx = ex2f(f1.x), qy = ex2f(f1.y);
            s2[1][kp] = pk2(qx, qy); l1 += qx + qy;
        }

        // ---- PV phase: U[2q][32g] += p * V  (keys follow the same rotation) ----
        #pragma unroll
        for (int tt = 0; tt < 4; tt++) {
            int kbase_t = ksub * 4 + rot[tt];          // rotated key base
            #pragma unroll
            for (int jp = 0; jp < 2; jp++) {
                float2 p0 = upk2(s2[0][tt * 2 + jp]);
                float2 p1 = upk2(s2[1][tt * 2 + jp]);
                #pragma unroll
                for (int j2 = 0; j2 < 2; j2++) {
                    int k = kbase_t + jp * 2 + j2;
                    float sp0 = j2 ? p0.y : p0.x;
                    float sp1 = j2 ? p1.y : p1.x;
                    u64 a0 = pk2(sp0, sp0), a1 = pk2(sp1, sp1);
                    const float* vr = vtb + k * 36;
                    #pragma unroll
                    for (int gi = 0; gi < 8; gi++) {
                        int pc = gi ^ ksub;
                        ulonglong2 vv = *(const ulonglong2*)(vr + pc * 4);
                        U2[0][2 * gi]     = fma2(a0, vv.x, U2[0][2 * gi]);
                        U2[0][2 * gi + 1] = fma2(a0, vv.y, U2[0][2 * gi + 1]);
                        U2[1][2 * gi]     = fma2(a1, vv.x, U2[1][2 * gi]);
                        U2[1][2 * gi + 1] = fma2(a1, vv.y, U2[1][2 * gi + 1]);
                    }
                }
            }
        }
        __syncthreads();
    }

    // ---- final: butterfly-reduce partial U and l over the 8 ksub lanes ----
    #pragma unroll
    for (int d = 1; d <= 4; d <<= 1) {
        l0 += __shfl_xor_sync(0xffffffffu, l0, d);
        l1 += __shfl_xor_sync(0xffffffffu, l1, d);
        #pragma unroll
        for (int q = 0; q < 2; q++)
            #pragma unroll
            for (int gp = 0; gp < 16; gp++) {
                u64 o = __shfl_xor_sync(0xffffffffu, U2[q][gp], d);
                U2[q][gp] = add2(U2[q][gp], o);
            }
    }
    float inv0 = 1.f / l0, inv1 = 1.f / l1;
    float* up = g_U + (bh * LSEQ + q0 + qb) * HAR + ksub * 4;
    {
        float2 A = upk2(U2[0][ksub * 2]), B2 = upk2(U2[0][ksub * 2 + 1]);
        float4 o0 = make_float4(A.x * inv0, A.y * inv0, B2.x * inv0, B2.y * inv0);
        *(float4*)up = o0;
        A = upk2(U2[1][ksub * 2]); B2 = upk2(U2[1][ksub * 2 + 1]);
        float4 o1 = make_float4(A.x * inv1, A.y * inv1, B2.x * inv1, B2.y * inv1);
        *(float4*)(up + HAR) = o1;
    }
}

// ---------------- K5: res_o[row][g] = sum_h sum_j U[b,h,l,j] * C_h[j][g] ----------------
__global__ __launch_bounds__(256) void k_mix() {
    __shared__ float sU[8 * 512];
    int t = threadIdx.x;
    int row0 = blockIdx.x * 8;
    for (int e = t; e < 4096; e += 256) {
        int r = e >> 9, rest = e & 511;
        int h = rest >> 5, j = rest & 31;
        int row = row0 + r;
        int b = row >> 11, l = row & (LSEQ - 1);
        sU[e] = g_U[((b * NH + h) * LSEQ + l) * HAR + j];
    }
    __syncthreads();
    int r = t >> 5, g = t & 31;
    float acc = 0.f;
    const float* cp = g_C;
    #pragma unroll 8
    for (int e = 0; e < 512; e++)
        acc += sU[r * 512 + e] * cp[e * 32 + g];
    g_ro[(row0 + r) * HAR + g] = acc;
}

// ---------------- K6: y[row][o] = sum_g res_o[row][g] * wo[o][g] ----------------
__global__ __launch_bounds__(256) void k_out(float* __restrict__ out) {
    __shared__ float sR[16 * 32];
    int t = threadIdx.x;
    int row0 = blockIdx.x * 16;
    for (int e = t; e < 512; e += 256) sR[e] = g_ro[row0 * HAR + e];
    __syncthreads();
    for (int o = t; o < DIMC; o += 256) {
        float w[32];
        #pragma unroll
        for (int g = 0; g < 32; g++) w[g] = g_wo[o * 32 + g];
        #pragma unroll 4
        for (int r = 0; r < 16; r++) {
            float acc = 0.f;
            #pragma unroll
            for (int g = 0; g < 32; g++) acc += sR[r * 32 + g] * w[g];
            out[(row0 + r) * DIMC + o] = acc;
        }
    }
}

extern "C" void kernel_launch(void* const* d_in, const int* in_sizes, int n_in,
                              void* d_out, int out_size) {
    const float* x   = (const float*)d_in[0];
    const float* bq  = (const float*)d_in[1];
    const float* pq  = (const float*)d_in[2];
    const float* aq  = (const float*)d_in[3];
    const float* bk  = (const float*)d_in[4];
    const float* pk_ = (const float*)d_in[5];
    const float* ak  = (const float*)d_in[6];
    const float* bv  = (const float*)d_in[7];
    const float* pv  = (const float*)d_in[8];
    const float* av  = (const float*)d_in[9];
    const float* bo  = (const float*)d_in[10];
    const float* po  = (const float*)d_in[11];
    const float* ao  = (const float*)d_in[12];
    float* out = (float*)d_out;

    const int attn_smem = (2 * KTBUF + 2 * VBUF + 32 * 34) * (int)sizeof(float);
    cudaFuncSetAttribute(k_attn, cudaFuncAttributeMaxDynamicSharedMemorySize, attn_smem);

    k_mc<<<NH, 1024>>>(aq, pq, ak, pk_, av, pv, bo);
    k_wo<<<32, 1024>>>(ao, po);
    k_res<<<BSZ * LSEQ / 32, 256>>>(x, bq, bk, bv);
    k_attn<<<dim3(LSEQ / 32, BSZ * NH), 128, attn_smem>>>();
    k_mix<<<BSZ * LSEQ / 8, 256>>>();
    k_out<<<BSZ * LSEQ / 16, 256>>>(out);
}

// round 11
// speedup vs baseline: 1.2652x; 1.2652x over previous
#include <cuda_runtime.h>

#define BSZ 2
#define LSEQ 2048
#define DIMC 1024
#define HAR 32
#define NH 16
#define HD 64
#define LOG2E 1.4426950408889634f
#define SCALE 0.125f

// ---------------- scratch (__device__ globals; no allocation allowed) ----------------
__device__ float g_res[3 * BSZ * LSEQ * HAR];   // res_q/res_k/res_v  [3][B][L][32]
__device__ float g_rkT[BSZ * HAR * LSEQ];       // res_k transposed   [B][32][L]
__device__ float g_M[NH * HAR * HAR];           // M_h[i][j] * scale * log2e
__device__ float g_C[NH * HAR * HAR];           // C_h[j][g]
__device__ float g_wo[DIMC * HAR];              // wo[o][g]
__device__ float g_U[BSZ * NH * LSEQ * HAR];    // attention U  [B][H][L][32]
__device__ float g_ro[BSZ * LSEQ * HAR];        // res_o        [B*L][32]

typedef unsigned long long u64;

__device__ __forceinline__ u64 pk2(float x, float y) {
    u64 r; asm("mov.b64 %0, {%1,%2};" : "=l"(r) : "f"(x), "f"(y)); return r;
}
__device__ __forceinline__ float2 upk2(u64 a) {
    float2 r; asm("mov.b64 {%0,%1}, %2;" : "=f"(r.x), "=f"(r.y) : "l"(a)); return r;
}
__device__ __forceinline__ u64 fma2(u64 a, u64 b, u64 c) {
    u64 d; asm("fma.rn.f32x2 %0, %1, %2, %3;" : "=l"(d) : "l"(a), "l"(b), "l"(c)); return d;
}
__device__ __forceinline__ u64 mul2(u64 a, u64 b) {
    u64 d; asm("mul.rn.f32x2 %0, %1, %2;" : "=l"(d) : "l"(a), "l"(b)); return d;
}
__device__ __forceinline__ u64 add2(u64 a, u64 b) {
    u64 d; asm("add.rn.f32x2 %0, %1, %2;" : "=l"(d) : "l"(a), "l"(b)); return d;
}
__device__ __forceinline__ float ex2f(float x) {
    float r; asm("ex2.approx.ftz.f32 %0, %1;" : "=f"(r) : "f"(x)); return r;
}
__device__ __forceinline__ void cpa16(unsigned dst, const void* src) {
    asm volatile("cp.async.cg.shared.global [%0], [%1], 16;" :: "r"(dst), "l"(src));
}
__device__ __forceinline__ void cpa_commit() {
    asm volatile("cp.async.commit_group;" ::: "memory");
}

// ---------------- K1: per-head M_h and C_h ----------------
__global__ void k_mc(const float* __restrict__ aq, const float* __restrict__ pq,
                     const float* __restrict__ ak, const float* __restrict__ pkh,
                     const float* __restrict__ av, const float* __restrict__ pv,
                     const float* __restrict__ bo) {
    int h = blockIdx.x, t = threadIdx.x;
    __shared__ float wq[HD * HAR], wk[HD * HAR], wv[HD * HAR], bos[HD * HAR];
    for (int e = t; e < HD * HAR; e += 1024) {
        int d = e >> 5, i = e & 31;
        int idx = (h * HD + d) * HAR + i;
        wq[e]  = aq[idx] * (float)cos((double)pq[idx]);   // fp64 cos: immune to fast_math
        wk[e]  = ak[idx] * (float)cos((double)pkh[idx]);
        wv[e]  = av[idx] * (float)cos((double)pv[idx]);
        bos[e] = bo[i * DIMC + h * HD + d];
    }
    __syncthreads();
    int i = t >> 5, j = t & 31;
    float m = 0.f, c = 0.f;
    #pragma unroll 8
    for (int d = 0; d < HD; d++) {
        m += wq[d * 32 + i] * wk[d * 32 + j];
        c += wv[d * 32 + i] * bos[d * 32 + j];
    }
    g_M[h * 1024 + t] = m * (SCALE * LOG2E);
    g_C[h * 1024 + t] = c;
}

// ---------------- K2: wo = amp_o * cos(phase_o) ----------------
__global__ void k_wo(const float* __restrict__ ao, const float* __restrict__ po) {
    int i = blockIdx.x * 1024 + threadIdx.x;
    g_wo[i] = ao[i] * (float)cos((double)po[i]);
}

// ---------------- K3: resonance GEMM  [4096,1024] x [1024,96] ----------------
__global__ __launch_bounds__(256) void k_res(const float* __restrict__ x,
                                             const float* __restrict__ bq,
                                             const float* __restrict__ bk,
                                             const float* __restrict__ bv) {
    __shared__ __align__(16) float As[32 * 33];
    __shared__ __align__(16) float Bs[32 * 97];
    int t = threadIdx.x;
    int r0 = blockIdx.x * 32;
    int tx = t & 15, ty = t >> 4;
    float acc[2][6];
    #pragma unroll
    for (int u = 0; u < 2; u++)
        #pragma unroll
        for (int c = 0; c < 6; c++) acc[u][c] = 0.f;

    for (int k0 = 0; k0 < DIMC; k0 += 32) {
        __syncthreads();
        {
            int row = t >> 3, c4 = (t & 7) * 4;
            float4 v = *(const float4*)(x + (r0 + row) * DIMC + k0 + c4);
            float* d = As + row * 33 + c4;
            d[0] = v.x; d[1] = v.y; d[2] = v.z; d[3] = v.w;
        }
        for (int f4 = t; f4 < 768; f4 += 256) {
            int n = f4 >> 3, c4 = (f4 & 7) * 4;
            const float* bp = (n < 32) ? (bq + n * DIMC)
                             : (n < 64) ? (bk + (n - 32) * DIMC)
                                        : (bv + (n - 64) * DIMC);
            float4 v = *(const float4*)(bp + k0 + c4);
            Bs[(c4 + 0) * 97 + n] = v.x;
            Bs[(c4 + 1) * 97 + n] = v.y;
            Bs[(c4 + 2) * 97 + n] = v.z;
            Bs[(c4 + 3) * 97 + n] = v.w;
        }
        __syncthreads();
        #pragma unroll
        for (int kk = 0; kk < 32; kk++) {
            float a0 = As[(ty * 2 + 0) * 33 + kk];
            float a1 = As[(ty * 2 + 1) * 33 + kk];
            #pragma unroll
            for (int c = 0; c < 6; c++) {
                float bb = Bs[kk * 97 + tx * 6 + c];
                acc[0][c] += a0 * bb;
                acc[1][c] += a1 * bb;
            }
        }
    }
    #pragma unroll
    for (int u = 0; u < 2; u++)
        #pragma unroll
        for (int c = 0; c < 6; c++) {
            int row = r0 + ty * 2 + u;
            int n = tx * 6 + c;
            int p = n >> 5, j = n & 31;
            int b = row >> 11, l = row & (LSEQ - 1);
            if (p == 1)
                g_rkT[(b * HAR + j) * LSEQ + l] = acc[u][c];     // K transposed
            else
                g_res[((p * BSZ + b) * LSEQ + l) * HAR + j] = acc[u][c];
        }
}

// ---------------- K4: fused flash attention on rank-32 factors ----------------
// grid (32 qtiles of 64, B*H=32), 128 threads = 4 warps.
// q_l = 4: lane (qsub,ksub) owns 4 queries x 16 keys; each K/V chunk loaded
// from smem feeds 4 queries (2x the FMA-per-byte of q_l=2). Warp covers
// 16 queries; block 64. Logits tiny (|S|<<1): plain exp2, no max subtraction.
#define KTBUF (32 * 132)
#define VBUF  (128 * 36)
#define GQPAD 68
__global__ __launch_bounds__(128, 2) void k_attn() {
    extern __shared__ __align__(16) float smem[];
    float* sKT = smem;                        // 2 x KTBUF
    float* sV  = smem + 2 * KTBUF;            // 2 x VBUF
    float* sGq = smem + 2 * KTBUF + 2 * VBUF; // 32 x GQPAD

    int t = threadIdx.x;
    int w = t >> 5, lane = t & 31;
    int qsub = lane >> 3, ksub = lane & 7;
    int q0 = blockIdx.x * 64;
    int bh = blockIdx.y;
    int b = bh >> 4, h = bh & 15;
    const float* rq  = g_res + (0 * BSZ + b) * LSEQ * HAR;
    const float* rv  = g_res + (2 * BSZ + b) * LSEQ * HAR;
    const float* rkT = g_rkT + b * HAR * LSEQ;

    // ---- stage tile 0 into buffer 0 ----
    {
        unsigned kbase = (unsigned)__cvta_generic_to_shared(sKT);
        unsigned vbase = (unsigned)__cvta_generic_to_shared(sV);
        #pragma unroll
        for (int it = 0; it < 8; it++) {
            int f4 = t + it * 128;
            int row = f4 >> 5, c = f4 & 31;
            cpa16(kbase + (row * 132 + c * 4) * 4, rkT + row * LSEQ + c * 4);
        }
        #pragma unroll
        for (int it = 0; it < 8; it++) {
            int f4 = t + it * 128;
            int key = f4 >> 3, gi = f4 & 7;
            int pc = gi ^ ((key >> 2) & 7);
            cpa16(vbase + (key * 36 + pc * 4) * 4, rv + key * HAR + gi * 4);
        }
        cpa_commit();
    }

    // ---- phase 0: Gq[64,32] = rq_tile * M, stored transposed in sGq[j][64] ----
    {
        int q = t >> 1, jb = (t & 1) * 16;
        const float* rqrow = rq + (q0 + q) * HAR;
        const float* Mrow = g_M + h * 1024;
        float a[16];
        #pragma unroll
        for (int jj = 0; jj < 16; jj++) a[jj] = 0.f;
        #pragma unroll 4
        for (int i = 0; i < 32; i++) {
            float qv = rqrow[i];
            #pragma unroll
            for (int jj = 0; jj < 16; jj++) a[jj] += qv * Mrow[i * 32 + jb + jj];
        }
        #pragma unroll
        for (int jj = 0; jj < 16; jj++) sGq[(jb + jj) * GQPAD + q] = a[jj];
    }

    u64 U2[4][16];
    #pragma unroll
    for (int q = 0; q < 4; q++)
        #pragma unroll
        for (int gp = 0; gp < 16; gp++) U2[q][gp] = 0ULL;
    float lac[4];
    #pragma unroll
    for (int q = 0; q < 4; q++) lac[q] = 0.f;
    int qb = w * 16 + qsub * 4;     // lane's first query (block-local)

    for (int kt = 0; kt < 16; kt++) {
        int cb = kt & 1;
        if (kt < 15) {       // stage next tile into the other buffer
            int nb = cb ^ 1;
            unsigned kbase = (unsigned)__cvta_generic_to_shared(sKT + nb * KTBUF);
            unsigned vbase = (unsigned)__cvta_generic_to_shared(sV + nb * VBUF);
            const float* rkTs = rkT + (kt + 1) * 128;
            const float* rvs  = rv + (kt + 1) * 128 * HAR;
            #pragma unroll
            for (int it = 0; it < 8; it++) {
                int f4 = t + it * 128;
                int row = f4 >> 5, c = f4 & 31;
                cpa16(kbase + (row * 132 + c * 4) * 4, rkTs + row * LSEQ + c * 4);
            }
            #pragma unroll
            for (int it = 0; it < 8; it++) {
                int f4 = t + it * 128;
                int key = f4 >> 3, gi = f4 & 7;
                int pc = gi ^ ((key >> 2) & 7);
                cpa16(vbase + (key * 36 + pc * 4) * 4, rvs + key * HAR + gi * 4);
            }
            cpa_commit();
            asm volatile("cp.async.wait_group 1;" ::: "memory");
        } else {
            asm volatile("cp.async.wait_group 0;" ::: "memory");
        }
        __syncthreads();

        const float* ktb = sKT + cb * KTBUF;
        const float* vtb = sV + cb * VBUF;

        // ---- S phase: s2[4q][8] pairs over adjacent keys ----
        u64 s2[4][8];
        #pragma unroll
        for (int q = 0; q < 4; q++)
            #pragma unroll
            for (int kp = 0; kp < 8; kp++) s2[q][kp] = 0ULL;
        #pragma unroll 8
        for (int kk = 0; kk < 32; kk++) {
            float4 gqv = *(const float4*)(sGq + kk * GQPAD + qb);  // 4 queries
            u64 a0 = pk2(gqv.x, gqv.x);
            u64 a1 = pk2(gqv.y, gqv.y);
            u64 a2 = pk2(gqv.z, gqv.z);
            u64 a3 = pk2(gqv.w, gqv.w);
            const float* kr = ktb + kk * 132 + ksub * 4;
            #pragma unroll
            for (int tt = 0; tt < 4; tt++) {
                ulonglong2 kv = *(const ulonglong2*)(kr + tt * 32);
                s2[0][tt * 2 + 0] = fma2(a0, kv.x, s2[0][tt * 2 + 0]);
                s2[0][tt * 2 + 1] = fma2(a0, kv.y, s2[0][tt * 2 + 1]);
                s2[1][tt * 2 + 0] = fma2(a1, kv.x, s2[1][tt * 2 + 0]);
                s2[1][tt * 2 + 1] = fma2(a1, kv.y, s2[1][tt * 2 + 1]);
                s2[2][tt * 2 + 0] = fma2(a2, kv.x, s2[2][tt * 2 + 0]);
                s2[2][tt * 2 + 1] = fma2(a2, kv.y, s2[2][tt * 2 + 1]);
                s2[3][tt * 2 + 0] = fma2(a3, kv.x, s2[3][tt * 2 + 0]);
                s2[3][tt * 2 + 1] = fma2(a3, kv.y, s2[3][tt * 2 + 1]);
            }
        }

        // ---- p = exp2(s) directly (logits tiny; no max subtraction needed) ----
        #pragma unroll
        for (int q = 0; q < 4; q++) {
            #pragma unroll
            for (int kp = 0; kp < 8; kp++) {
                float2 f = upk2(s2[q][kp]);
                float px = ex2f(f.x), py = ex2f(f.y);
                s2[q][kp] = pk2(px, py);
                lac[q] += px + py;
            }
        }

        // ---- PV phase: U[4q][32g] += p * V ----
        #pragma unroll
        for (int tt = 0; tt < 4; tt++) {
            #pragma unroll
            for (int jp = 0; jp < 2; jp++) {
                float2 p0 = upk2(s2[0][tt * 2 + jp]);
                float2 p1 = upk2(s2[1][tt * 2 + jp]);
                float2 p2 = upk2(s2[2][tt * 2 + jp]);
                float2 p3 = upk2(s2[3][tt * 2 + jp]);
                #pragma unroll
                for (int j2 = 0; j2 < 2; j2++) {
                    int k = ksub * 4 + tt * 32 + jp * 2 + j2;
                    u64 a0 = j2 ? pk2(p0.y, p0.y) : pk2(p0.x, p0.x);
                    u64 a1 = j2 ? pk2(p1.y, p1.y) : pk2(p1.x, p1.x);
                    u64 a2 = j2 ? pk2(p2.y, p2.y) : pk2(p2.x, p2.x);
                    u64 a3 = j2 ? pk2(p3.y, p3.y) : pk2(p3.x, p3.x);
                    const float* vr = vtb + k * 36;
                    #pragma unroll
                    for (int gi = 0; gi < 8; gi++) {
                        int pc = gi ^ ksub;
                        ulonglong2 vv = *(const ulonglong2*)(vr + pc * 4);
                        U2[0][2 * gi]     = fma2(a0, vv.x, U2[0][2 * gi]);
                        U2[0][2 * gi + 1] = fma2(a0, vv.y, U2[0][2 * gi + 1]);
                        U2[1][2 * gi]     = fma2(a1, vv.x, U2[1][2 * gi]);
                        U2[1][2 * gi + 1] = fma2(a1, vv.y, U2[1][2 * gi + 1]);
                        U2[2][2 * gi]     = fma2(a2, vv.x, U2[2][2 * gi]);
                        U2[2][2 * gi + 1] = fma2(a2, vv.y, U2[2][2 * gi + 1]);
                        U2[3][2 * gi]     = fma2(a3, vv.x, U2[3][2 * gi]);
                        U2[3][2 * gi + 1] = fma2(a3, vv.y, U2[3][2 * gi + 1]);
                    }
                }
            }
        }
        __syncthreads();
    }

    // ---- final: butterfly-reduce partial U and l over the 8 ksub lanes ----
    #pragma unroll
    for (int d = 1; d <= 4; d <<= 1) {
        #pragma unroll
        for (int q = 0; q < 4; q++) {
            lac[q] += __shfl_xor_sync(0xffffffffu, lac[q], d);
            #pragma unroll
            for (int gp = 0; gp < 16; gp++) {
                u64 o = __shfl_xor_sync(0xffffffffu, U2[q][gp], d);
                U2[q][gp] = add2(U2[q][gp], o);
            }
        }
    }
    #pragma unroll
    for (int q = 0; q < 4; q++) {
        float inv = 1.f / lac[q];
        float* up = g_U + (bh * LSEQ + q0 + qb + q) * HAR + ksub * 4;
        float2 A = upk2(U2[q][ksub * 2]), B2 = upk2(U2[q][ksub * 2 + 1]);
        *(float4*)up = make_float4(A.x * inv, A.y * inv, B2.x * inv, B2.y * inv);
    }
}

// ---------------- K5: res_o[row][g] = sum_h sum_j U[b,h,l,j] * C_h[j][g] ----------------
__global__ __launch_bounds__(256) void k_mix() {
    __shared__ float sU[8 * 512];
    int t = threadIdx.x;
    int row0 = blockIdx.x * 8;
    for (int e = t; e < 4096; e += 256) {
        int r = e >> 9, rest = e & 511;
        int h = rest >> 5, j = rest & 31;
        int row = row0 + r;
        int b = row >> 11, l = row & (LSEQ - 1);
        sU[e] = g_U[((b * NH + h) * LSEQ + l) * HAR + j];
    }
    __syncthreads();
    int r = t >> 5, g = t & 31;
    float acc = 0.f;
    const float* cp = g_C;
    #pragma unroll 8
    for (int e = 0; e < 512; e++)
        acc += sU[r * 512 + e] * cp[e * 32 + g];
    g_ro[(row0 + r) * HAR + g] = acc;
}

// ---------------- K6: y[row][o] = sum_g res_o[row][g] * wo[o][g] ----------------
__global__ __launch_bounds__(256) void k_out(float* __restrict__ out) {
    __shared__ float sR[16 * 32];
    int t = threadIdx.x;
    int row0 = blockIdx.x * 16;
    for (int e = t; e < 512; e += 256) sR[e] = g_ro[row0 * HAR + e];
    __syncthreads();
    for (int o = t; o < DIMC; o += 256) {
        float w[32];
        #pragma unroll
        for (int g = 0; g < 32; g++) w[g] = g_wo[o * 32 + g];
        #pragma unroll 4
        for (int r = 0; r < 16; r++) {
            float acc = 0.f;
            #pragma unroll
            for (int g = 0; g < 32; g++) acc += sR[r * 32 + g] * w[g];
            out[(row0 + r) * DIMC + o] = acc;
        }
    }
}

extern "C" void kernel_launch(void* const* d_in, const int* in_sizes, int n_in,
                              void* d_out, int out_size) {
    const float* x   = (const float*)d_in[0];
    const float* bq  = (const float*)d_in[1];
    const float* pq  = (const float*)d_in[2];
    const float* aq  = (const float*)d_in[3];
    const float* bk  = (const float*)d_in[4];
    const float* pk_ = (const float*)d_in[5];
    const float* ak  = (const float*)d_in[6];
    const float* bv  = (const float*)d_in[7];
    const float* pv  = (const float*)d_in[8];
    const float* av  = (const float*)d_in[9];
    const float* bo  = (const float*)d_in[10];
    const float* po  = (const float*)d_in[11];
    const float* ao  = (const float*)d_in[12];
    float* out = (float*)d_out;

    const int attn_smem = (2 * KTBUF + 2 * VBUF + 32 * GQPAD) * (int)sizeof(float);
    cudaFuncSetAttribute(k_attn, cudaFuncAttributeMaxDynamicSharedMemorySize, attn_smem);

    k_mc<<<NH, 1024>>>(aq, pq, ak, pk_, av, pv, bo);
    k_wo<<<32, 1024>>>(ao, po);
    k_res<<<BSZ * LSEQ / 32, 256>>>(x, bq, bk, bv);
    k_attn<<<dim3(LSEQ / 64, BSZ * NH), 128, attn_smem>>>();
    k_mix<<<BSZ * LSEQ / 8, 256>>>();
    k_out<<<BSZ * LSEQ / 16, 256>>>(out);
}

// round 12
// speedup vs baseline: 1.2746x; 1.0074x over previous
#include <cuda_runtime.h>

#define BSZ 2
#define LSEQ 2048
#define DIMC 1024
#define HAR 32
#define NH 16
#define HD 64
#define LOG2E 1.4426950408889634f
#define SCALE 0.125f

// ---------------- scratch (__device__ globals; no allocation allowed) ----------------
__device__ __align__(16) float g_res[3 * BSZ * LSEQ * HAR];   // res_q/res_k/res_v
__device__ __align__(16) float g_rkT[BSZ * HAR * LSEQ];       // res_k transposed [B][32][L]
__device__ __align__(16) float g_M[NH * HAR * HAR];           // M_h[i][j] * scale * log2e
__device__ __align__(16) float g_C[NH * HAR * HAR];           // C_h[j][g]
__device__ __align__(16) float g_wo[DIMC * HAR];              // wo[o][g]
__device__ __align__(16) float g_U[BSZ * NH * LSEQ * HAR];    // attention U [B][H][L][32]

typedef unsigned long long u64;

__device__ __forceinline__ u64 pk2(float x, float y) {
    u64 r; asm("mov.b64 %0, {%1,%2};" : "=l"(r) : "f"(x), "f"(y)); return r;
}
__device__ __forceinline__ float2 upk2(u64 a) {
    float2 r; asm("mov.b64 {%0,%1}, %2;" : "=f"(r.x), "=f"(r.y) : "l"(a)); return r;
}
__device__ __forceinline__ u64 fma2(u64 a, u64 b, u64 c) {
    u64 d; asm("fma.rn.f32x2 %0, %1, %2, %3;" : "=l"(d) : "l"(a), "l"(b), "l"(c)); return d;
}
__device__ __forceinline__ u64 add2(u64 a, u64 b) {
    u64 d; asm("add.rn.f32x2 %0, %1, %2;" : "=l"(d) : "l"(a), "l"(b)); return d;
}
__device__ __forceinline__ float ex2f(float x) {
    float r; asm("ex2.approx.ftz.f32 %0, %1;" : "=f"(r) : "f"(x)); return r;
}
__device__ __forceinline__ void cpa16(unsigned dst, const void* src) {
    asm volatile("cp.async.cg.shared.global [%0], [%1], 16;" :: "r"(dst), "l"(src));
}
__device__ __forceinline__ void cpa_commit() {
    asm volatile("cp.async.commit_group;" ::: "memory");
}

// ---------------- K1: per-head M_h and C_h ----------------
__global__ void k_mc(const float* __restrict__ aq, const float* __restrict__ pq,
                     const float* __restrict__ ak, const float* __restrict__ pkh,
                     const float* __restrict__ av, const float* __restrict__ pv,
                     const float* __restrict__ bo) {
    int h = blockIdx.x, t = threadIdx.x;
    __shared__ float wq[HD * HAR], wk[HD * HAR], wv[HD * HAR], bos[HD * HAR];
    for (int e = t; e < HD * HAR; e += 1024) {
        int d = e >> 5, i = e & 31;
        int idx = (h * HD + d) * HAR + i;
        wq[e]  = aq[idx] * (float)cos((double)pq[idx]);   // fp64 cos: immune to fast_math
        wk[e]  = ak[idx] * (float)cos((double)pkh[idx]);
        wv[e]  = av[idx] * (float)cos((double)pv[idx]);
        bos[e] = bo[i * DIMC + h * HD + d];
    }
    __syncthreads();
    int i = t >> 5, j = t & 31;
    float m = 0.f, c = 0.f;
    #pragma unroll 8
    for (int d = 0; d < HD; d++) {
        m += wq[d * 32 + i] * wk[d * 32 + j];
        c += wv[d * 32 + i] * bos[d * 32 + j];
    }
    g_M[h * 1024 + t] = m * (SCALE * LOG2E);
    g_C[h * 1024 + t] = c;
}

// ---------------- K2: wo = amp_o * cos(phase_o) ----------------
__global__ void k_wo(const float* __restrict__ ao, const float* __restrict__ po) {
    int i = blockIdx.x * 1024 + threadIdx.x;
    g_wo[i] = ao[i] * (float)cos((double)po[i]);
}

// ---------------- K3: resonance GEMM  [4096,1024] x [1024,96] (f32x2 packed) ----------------
__global__ __launch_bounds__(256) void k_res(const float* __restrict__ x,
                                             const float* __restrict__ bq,
                                             const float* __restrict__ bk,
                                             const float* __restrict__ bv) {
    __shared__ __align__(16) float Ast[32 * 34];   // [kk][row], pad 34 (even -> aligned pairs)
    __shared__ __align__(16) float Bs[32 * 98];    // [kk][n],  pad 98 (even -> aligned pairs)
    int t = threadIdx.x;
    int r0 = blockIdx.x * 32;
    int tx = t & 15, ty = t >> 4;
    u64 acc[2][3];
    #pragma unroll
    for (int u = 0; u < 2; u++)
        #pragma unroll
        for (int cp = 0; cp < 3; cp++) acc[u][cp] = 0ULL;

    for (int k0 = 0; k0 < DIMC; k0 += 32) {
        __syncthreads();
        {   // A tile, stored transposed: Ast[kk][row]
            int row = t >> 3, c4 = (t & 7) * 4;
            float4 v = *(const float4*)(x + (r0 + row) * DIMC + k0 + c4);
            Ast[(c4 + 0) * 34 + row] = v.x;
            Ast[(c4 + 1) * 34 + row] = v.y;
            Ast[(c4 + 2) * 34 + row] = v.z;
            Ast[(c4 + 3) * 34 + row] = v.w;
        }
        for (int f4 = t; f4 < 768; f4 += 256) {
            int n = f4 >> 3, c4 = (f4 & 7) * 4;
            const float* bp = (n < 32) ? (bq + n * DIMC)
                             : (n < 64) ? (bk + (n - 32) * DIMC)
                                        : (bv + (n - 64) * DIMC);
            float4 v = *(const float4*)(bp + k0 + c4);
            Bs[(c4 + 0) * 98 + n] = v.x;
            Bs[(c4 + 1) * 98 + n] = v.y;
            Bs[(c4 + 2) * 98 + n] = v.z;
            Bs[(c4 + 3) * 98 + n] = v.w;
        }
        __syncthreads();
        #pragma unroll
        for (int kk = 0; kk < 32; kk++) {
            float a0 = Ast[kk * 34 + ty * 2];        // broadcast
            float a1 = Ast[kk * 34 + ty * 2 + 1];
            u64 a02 = pk2(a0, a0), a12 = pk2(a1, a1);
            const u64* bp2 = (const u64*)(Bs + kk * 98 + tx * 6);
            #pragma unroll
            for (int cp = 0; cp < 3; cp++) {
                u64 b2 = bp2[cp];
                acc[0][cp] = fma2(a02, b2, acc[0][cp]);
                acc[1][cp] = fma2(a12, b2, acc[1][cp]);
            }
        }
    }
    #pragma unroll
    for (int u = 0; u < 2; u++)
        #pragma unroll
        for (int cp = 0; cp < 3; cp++) {
            float2 f = upk2(acc[u][cp]);
            int row = r0 + ty * 2 + u;
            int b = row >> 11, l = row & (LSEQ - 1);
            #pragma unroll
            for (int j2 = 0; j2 < 2; j2++) {
                int n = tx * 6 + cp * 2 + j2;
                float val = j2 ? f.y : f.x;
                int p = n >> 5, j = n & 31;
                if (p == 1)
                    g_rkT[(b * HAR + j) * LSEQ + l] = val;     // K transposed
                else
                    g_res[((p * BSZ + b) * LSEQ + l) * HAR + j] = val;
            }
        }
}

// ---------------- K4: fused flash attention on rank-32 factors (FROZEN from R10) ----------------
#define KTBUF (32 * 132)
#define VBUF  (128 * 36)
#define GQPAD 68
__global__ __launch_bounds__(128, 2) void k_attn() {
    extern __shared__ __align__(16) float smem[];
    float* sKT = smem;                        // 2 x KTBUF
    float* sV  = smem + 2 * KTBUF;            // 2 x VBUF
    float* sGq = smem + 2 * KTBUF + 2 * VBUF; // 32 x GQPAD

    int t = threadIdx.x;
    int w = t >> 5, lane = t & 31;
    int qsub = lane >> 3, ksub = lane & 7;
    int q0 = blockIdx.x * 64;
    int bh = blockIdx.y;
    int b = bh >> 4, h = bh & 15;
    const float* rq  = g_res + (0 * BSZ + b) * LSEQ * HAR;
    const float* rv  = g_res + (2 * BSZ + b) * LSEQ * HAR;
    const float* rkT = g_rkT + b * HAR * LSEQ;

    {
        unsigned kbase = (unsigned)__cvta_generic_to_shared(sKT);
        unsigned vbase = (unsigned)__cvta_generic_to_shared(sV);
        #pragma unroll
        for (int it = 0; it < 8; it++) {
            int f4 = t + it * 128;
            int row = f4 >> 5, c = f4 & 31;
            cpa16(kbase + (row * 132 + c * 4) * 4, rkT + row * LSEQ + c * 4);
        }
        #pragma unroll
        for (int it = 0; it < 8; it++) {
            int f4 = t + it * 128;
            int key = f4 >> 3, gi = f4 & 7;
            int pc = gi ^ ((key >> 2) & 7);
            cpa16(vbase + (key * 36 + pc * 4) * 4, rv + key * HAR + gi * 4);
        }
        cpa_commit();
    }

    {   // Gq[64,32] = rq_tile * M, stored transposed
        int q = t >> 1, jb = (t & 1) * 16;
        const float* rqrow = rq + (q0 + q) * HAR;
        const float* Mrow = g_M + h * 1024;
        float a[16];
        #pragma unroll
        for (int jj = 0; jj < 16; jj++) a[jj] = 0.f;
        #pragma unroll 4
        for (int i = 0; i < 32; i++) {
            float qv = rqrow[i];
            #pragma unroll
            for (int jj = 0; jj < 16; jj++) a[jj] += qv * Mrow[i * 32 + jb + jj];
        }
        #pragma unroll
        for (int jj = 0; jj < 16; jj++) sGq[(jb + jj) * GQPAD + q] = a[jj];
    }

    u64 U2[4][16];
    #pragma unroll
    for (int q = 0; q < 4; q++)
        #pragma unroll
        for (int gp = 0; gp < 16; gp++) U2[q][gp] = 0ULL;
    float lac[4];
    #pragma unroll
    for (int q = 0; q < 4; q++) lac[q] = 0.f;
    int qb = w * 16 + qsub * 4;

    for (int kt = 0; kt < 16; kt++) {
        int cb = kt & 1;
        if (kt < 15) {
            int nb = cb ^ 1;
            unsigned kbase = (unsigned)__cvta_generic_to_shared(sKT + nb * KTBUF);
            unsigned vbase = (unsigned)__cvta_generic_to_shared(sV + nb * VBUF);
            const float* rkTs = rkT + (kt + 1) * 128;
            const float* rvs  = rv + (kt + 1) * 128 * HAR;
            #pragma unroll
            for (int it = 0; it < 8; it++) {
                int f4 = t + it * 128;
                int row = f4 >> 5, c = f4 & 31;
                cpa16(kbase + (row * 132 + c * 4) * 4, rkTs + row * LSEQ + c * 4);
            }
            #pragma unroll
            for (int it = 0; it < 8; it++) {
                int f4 = t + it * 128;
                int key = f4 >> 3, gi = f4 & 7;
                int pc = gi ^ ((key >> 2) & 7);
                cpa16(vbase + (key * 36 + pc * 4) * 4, rvs + key * HAR + gi * 4);
            }
            cpa_commit();
            asm volatile("cp.async.wait_group 1;" ::: "memory");
        } else {
            asm volatile("cp.async.wait_group 0;" ::: "memory");
        }
        __syncthreads();

        const float* ktb = sKT + cb * KTBUF;
        const float* vtb = sV + cb * VBUF;

        u64 s2[4][8];
        #pragma unroll
        for (int q = 0; q < 4; q++)
            #pragma unroll
            for (int kp = 0; kp < 8; kp++) s2[q][kp] = 0ULL;
        #pragma unroll 8
        for (int kk = 0; kk < 32; kk++) {
            float4 gqv = *(const float4*)(sGq + kk * GQPAD + qb);
            u64 a0 = pk2(gqv.x, gqv.x);
            u64 a1 = pk2(gqv.y, gqv.y);
            u64 a2 = pk2(gqv.z, gqv.z);
            u64 a3 = pk2(gqv.w, gqv.w);
            const float* kr = ktb + kk * 132 + ksub * 4;
            #pragma unroll
            for (int tt = 0; tt < 4; tt++) {
                ulonglong2 kv = *(const ulonglong2*)(kr + tt * 32);
                s2[0][tt * 2 + 0] = fma2(a0, kv.x, s2[0][tt * 2 + 0]);
                s2[0][tt * 2 + 1] = fma2(a0, kv.y, s2[0][tt * 2 + 1]);
                s2[1][tt * 2 + 0] = fma2(a1, kv.x, s2[1][tt * 2 + 0]);
                s2[1][tt * 2 + 1] = fma2(a1, kv.y, s2[1][tt * 2 + 1]);
                s2[2][tt * 2 + 0] = fma2(a2, kv.x, s2[2][tt * 2 + 0]);
                s2[2][tt * 2 + 1] = fma2(a2, kv.y, s2[2][tt * 2 + 1]);
                s2[3][tt * 2 + 0] = fma2(a3, kv.x, s2[3][tt * 2 + 0]);
                s2[3][tt * 2 + 1] = fma2(a3, kv.y, s2[3][tt * 2 + 1]);
            }
        }

        #pragma unroll
        for (int q = 0; q < 4; q++) {
            #pragma unroll
            for (int kp = 0; kp < 8; kp++) {
                float2 f = upk2(s2[q][kp]);
                float px = ex2f(f.x), py = ex2f(f.y);
                s2[q][kp] = pk2(px, py);
                lac[q] += px + py;
            }
        }

        #pragma unroll
        for (int tt = 0; tt < 4; tt++) {
            #pragma unroll
            for (int jp = 0; jp < 2; jp++) {
                float2 p0 = upk2(s2[0][tt * 2 + jp]);
                float2 p1 = upk2(s2[1][tt * 2 + jp]);
                float2 p2 = upk2(s2[2][tt * 2 + jp]);
                float2 p3 = upk2(s2[3][tt * 2 + jp]);
                #pragma unroll
                for (int j2 = 0; j2 < 2; j2++) {
                    int k = ksub * 4 + tt * 32 + jp * 2 + j2;
                    u64 a0 = j2 ? pk2(p0.y, p0.y) : pk2(p0.x, p0.x);
                    u64 a1 = j2 ? pk2(p1.y, p1.y) : pk2(p1.x, p1.x);
                    u64 a2 = j2 ? pk2(p2.y, p2.y) : pk2(p2.x, p2.x);
                    u64 a3 = j2 ? pk2(p3.y, p3.y) : pk2(p3.x, p3.x);
                    const float* vr = vtb + k * 36;
                    #pragma unroll
                    for (int gi = 0; gi < 8; gi++) {
                        int pc = gi ^ ksub;
                        ulonglong2 vv = *(const ulonglong2*)(vr + pc * 4);
                        U2[0][2 * gi]     = fma2(a0, vv.x, U2[0][2 * gi]);
                        U2[0][2 * gi + 1] = fma2(a0, vv.y, U2[0][2 * gi + 1]);
                        U2[1][2 * gi]     = fma2(a1, vv.x, U2[1][2 * gi]);
                        U2[1][2 * gi + 1] = fma2(a1, vv.y, U2[1][2 * gi + 1]);
                        U2[2][2 * gi]     = fma2(a2, vv.x, U2[2][2 * gi]);
                        U2[2][2 * gi + 1] = fma2(a2, vv.y, U2[2][2 * gi + 1]);
                        U2[3][2 * gi]     = fma2(a3, vv.x, U2[3][2 * gi]);
                        U2[3][2 * gi + 1] = fma2(a3, vv.y, U2[3][2 * gi + 1]);
                    }
                }
            }
        }
        __syncthreads();
    }

    #pragma unroll
    for (int d = 1; d <= 4; d <<= 1) {
        #pragma unroll
        for (int q = 0; q < 4; q++) {
            lac[q] += __shfl_xor_sync(0xffffffffu, lac[q], d);
            #pragma unroll
            for (int gp = 0; gp < 16; gp++) {
                u64 o = __shfl_xor_sync(0xffffffffu, U2[q][gp], d);
                U2[q][gp] = add2(U2[q][gp], o);
            }
        }
    }
    #pragma unroll
    for (int q = 0; q < 4; q++) {
        float inv = 1.f / lac[q];
        float* up = g_U + (bh * LSEQ + q0 + qb + q) * HAR + ksub * 4;
        float2 A = upk2(U2[q][ksub * 2]), B2 = upk2(U2[q][ksub * 2 + 1]);
        *(float4*)up = make_float4(A.x * inv, A.y * inv, B2.x * inv, B2.y * inv);
    }
}

// ---------------- K5 (fused mix+out): 16 rows/block ----------------
// phase1: res_o[16,32] = sum_{h,j} U * C (2 rows packed per fma2)
// phase2: y[16,1024]  = res_o * wo^T   (g-pairs packed per fma2)
__global__ __launch_bounds__(256) void k_mixout(float* __restrict__ out) {
    __shared__ __align__(16) float sU[16 * 512];
    __shared__ __align__(16) float sR[16 * 32];
    int t = threadIdx.x;
    int row0 = blockIdx.x * 16;
    int b = row0 >> 11, l0 = row0 & (LSEQ - 1);
    for (int idx = t; idx < 16 * 512; idx += 256) {
        int r = idx >> 9, rest = idx & 511;
        int h = rest >> 5, j = rest & 31;
        sU[idx] = g_U[((b * NH + h) * LSEQ + (l0 + r)) * HAR + j];
    }
    __syncthreads();
    {
        int rp = t >> 5, g = t & 31;
        const float* cp = g_C;
        const float* u0 = sU + (2 * rp) * 512;
        const float* u1 = sU + (2 * rp + 1) * 512;
        u64 acc = 0ULL;
        #pragma unroll 8
        for (int e = 0; e < 512; e++) {
            u64 av = pk2(u0[e], u1[e]);          // broadcast loads
            float c = cp[e * 32 + g];            // coalesced
            acc = fma2(av, pk2(c, c), acc);
        }
        float2 f = upk2(acc);
        sR[(2 * rp) * 32 + g] = f.x;
        sR[(2 * rp + 1) * 32 + g] = f.y;
    }
    __syncthreads();
    for (int o = t; o < DIMC; o += 256) {
        const u64* wp = (const u64*)(g_wo + o * 32);
        u64 w2[16];
        #pragma unroll
        for (int gp = 0; gp < 16; gp++) w2[gp] = wp[gp];
        #pragma unroll 4
        for (int r = 0; r < 16; r++) {
            const u64* sp = (const u64*)(sR + r * 32);
            u64 acc = 0ULL;
            #pragma unroll
            for (int gp = 0; gp < 16; gp++) acc = fma2(sp[gp], w2[gp], acc);
            float2 f = upk2(acc);
            out[(row0 + r) * DIMC + o] = f.x + f.y;
        }
    }
}

extern "C" void kernel_launch(void* const* d_in, const int* in_sizes, int n_in,
                              void* d_out, int out_size) {
    const float* x   = (const float*)d_in[0];
    const float* bq  = (const float*)d_in[1];
    const float* pq  = (const float*)d_in[2];
    const float* aq  = (const float*)d_in[3];
    const float* bk  = (const float*)d_in[4];
    const float* pk_ = (const float*)d_in[5];
    const float* ak  = (const float*)d_in[6];
    const float* bv  = (const float*)d_in[7];
    const float* pv  = (const float*)d_in[8];
    const float* av  = (const float*)d_in[9];
    const float* bo  = (const float*)d_in[10];
    const float* po  = (const float*)d_in[11];
    const float* ao  = (const float*)d_in[12];
    float* out = (float*)d_out;

    const int attn_smem = (2 * KTBUF + 2 * VBUF + 32 * GQPAD) * (int)sizeof(float);
    cudaFuncSetAttribute(k_attn, cudaFuncAttributeMaxDynamicSharedMemorySize, attn_smem);

    k_mc<<<NH, 1024>>>(aq, pq, ak, pk_, av, pv, bo);
    k_wo<<<32, 1024>>>(ao, po);
    k_res<<<BSZ * LSEQ / 32, 256>>>(x, bq, bk, bv);
    k_attn<<<dim3(LSEQ / 64, BSZ * NH), 128, attn_smem>>>();
    k_mixout<<<BSZ * LSEQ / 16, 256>>>(out);
}